// round 5
// baseline (speedup 1.0000x reference)
#include <cuda_runtime.h>
#include <cstdint>

#define S_TOTAL 524288
#define ROW_F   48      // floats per s-row in x
#define TILE    128     // rows per block == threads per block
#define SSTRIDE 52      // padded smem row stride (floats): 16B-aligned, 4-way LDS conflict

// out layout: action_probs (2, S, 3) then p_values (2, 28, S)
__global__ __launch_bounds__(TILE)
void ump_kernel(const float* __restrict__ x,
                const float* __restrict__ action,
                const unsigned char* __restrict__ mask,
                const float* __restrict__ pb,
                float* __restrict__ out)
{
    __shared__ float sm[TILE * SSTRIDE];   // 26624 B

    const size_t S = (size_t)S_TOTAL;
    const int tid = threadIdx.x;
    const int tile_base = blockIdx.x * TILE;           // first s of this block

    // ---- stage 128 rows (24 KB) with coalesced float4 loads ----
    const float* gbase = x + (size_t)tile_base * ROW_F;
#pragma unroll
    for (int k = 0; k < (TILE * ROW_F) / (4 * TILE); k++) {   // 12 iters
        int f = k * TILE + tid;              // float4 index within tile
        int gf = f * 4;                      // float index within tile
        float4 val = __ldcs(reinterpret_cast<const float4*>(gbase + gf));
        int row = gf / ROW_F;
        int col = gf % ROW_F;                // multiple of 4 (48 % 4 == 0)
        *reinterpret_cast<float4*>(&sm[row * SSTRIDE + col]) = val;
    }
    __syncthreads();

    // ---- per-thread compute on its own row ----
    const int s = tile_base + tid;
    const float* r = &sm[tid * SSTRIDE];

    float2 v[8];
#pragma unroll
    for (int j = 0; j < 8; j++)
        v[j] = *reinterpret_cast<const float2*>(r + j * 6);

    // combined interval (both predicate flags true)
    float lo = fmaxf(pb[0], pb[2]);
    float hi = fminf(pb[1], pb[3]);

    bool any_sat = false;
    bool enemy_exist = true;
    float d[7][2];
#pragma unroll
    for (int p = 0; p < 7; p++) {
        float d0 = fabsf(v[0].x - v[p + 1].x);
        float d1 = fabsf(v[0].y - v[p + 1].y);
        d[p][0] = d0;
        d[p][1] = d1;
        any_sat = any_sat || (d0 >= lo && d0 <= hi) || (d1 >= lo && d1 <= hi);
        enemy_exist = enemy_exist && (v[p + 1].y > 0.8f);
    }

    bool m0 = mask[0] != 0;
    bool m1 = mask[1] != 0;
    bool satisfies = any_sat && ((v[0].x > 0.8f) == m0) && (enemy_exist == m1);

    float a0 = action[0], a1 = action[1], a2 = action[2];
    float w0 = satisfies ? (a0 / (a0 + 1e-20f)) : 0.0f;
    float w1 = satisfies ? (a1 / (a1 + 1e-20f)) : 0.0f;
    float w2 = satisfies ? (a2 / (a2 + 1e-20f)) : 0.0f;

    // action_probs: (2, S, 3) — identical for both type slices
    {
        float* ap0 = out + (size_t)s * 3;
        float* ap1 = ap0 + 3 * S;
        __stcs(ap0 + 0, w0); __stcs(ap0 + 1, w1); __stcs(ap0 + 2, w2);
        __stcs(ap1 + 0, w0); __stcs(ap1 + 1, w1); __stcs(ap1 + 2, w2);
    }

    // p_values: offset 6S, shape (2, 28, S); row = p*4 + k*2 + j
    float* __restrict__ pv = out + 6 * S;
#pragma unroll
    for (int p = 0; p < 7; p++) {
#pragma unroll
        for (int k = 0; k < 2; k++) {
            float val = d[p][k];
            size_t rr = (size_t)(p * 4 + k * 2);
            __stcs(pv + (rr + 0) * S + s, val);
            __stcs(pv + (rr + 1) * S + s, val);
            __stcs(pv + (rr + 28) * S + s, val);
            __stcs(pv + (rr + 29) * S + s, val);
        }
    }
}

extern "C" void kernel_launch(void* const* d_in, const int* in_sizes, int n_in,
                              void* d_out, int out_size)
{
    const float* x = (const float*)d_in[0];
    const float* action = (const float*)d_in[1];
    const unsigned char* mask = (const unsigned char*)d_in[2];
    const float* pb = (const float*)d_in[3];
    float* out = (float*)d_out;

    ump_kernel<<<S_TOTAL / TILE, TILE>>>(x, action, mask, pb, out);
}

// round 6
// speedup vs baseline: 1.0468x; 1.0468x over previous
#include <cuda_runtime.h>
#include <cstdint>

#define S_TOTAL 524288
#define N_PROP 6
#define N_OBJ 8

// out layout: action_probs (2, S, 3) then p_values (2, 28, S)
__global__ __launch_bounds__(512)
void ump_kernel(const float* __restrict__ x,
                const float* __restrict__ action,
                const unsigned char* __restrict__ mask,
                const float* __restrict__ pb,
                float* __restrict__ out)
{
    int s = blockIdx.x * blockDim.x + threadIdx.x;
    if (s >= S_TOTAL) return;

    const float* row = x + (size_t)s * (N_OBJ * N_PROP);

    // load props 0,1 of each of the 8 objects (8B-aligned float2, stride 24B)
    // streaming: no reuse across threads beyond the same 128B lines in-flight
    float2 v[N_OBJ];
#pragma unroll
    for (int j = 0; j < N_OBJ; j++) {
        v[j] = __ldcs(reinterpret_cast<const float2*>(row + j * N_PROP));
    }

    // existence
    bool enemy_exist = true;
#pragma unroll
    for (int j = 1; j < N_OBJ; j++) enemy_exist = enemy_exist && (v[j].y > 0.8f);
    bool m0 = mask[0] != 0;
    bool m1 = mask[1] != 0;
    bool exist_satisfy = ((v[0].x > 0.8f) == m0) && (enemy_exist == m1);

    // combined interval (both predicate flags are true)
    float lo = fmaxf(pb[0], pb[2]);
    float hi = fminf(pb[1], pb[3]);

    float d[7][2];
    bool any_sat = false;
#pragma unroll
    for (int p = 0; p < 7; p++) {
        float d0 = fabsf(v[0].x - v[p + 1].x);
        float d1 = fabsf(v[0].y - v[p + 1].y);
        d[p][0] = d0;
        d[p][1] = d1;
        any_sat = any_sat || (d0 >= lo && d0 <= hi) || (d1 >= lo && d1 <= hi);
    }
    bool satisfies = any_sat && exist_satisfy;

    float a0 = action[0], a1 = action[1], a2 = action[2];
    float w0 = satisfies ? (a0 / (a0 + 1e-20f)) : 0.0f;
    float w1 = satisfies ? (a1 / (a1 + 1e-20f)) : 0.0f;
    float w2 = satisfies ? (a2 / (a2 + 1e-20f)) : 0.0f;

    const size_t S = (size_t)S_TOTAL;

    // action_probs: [t, s, c], t in {0,1} — identical for both types
    {
        float* ap0 = out + (size_t)s * 3;
        float* ap1 = ap0 + 3 * S;
        __stcs(ap0 + 0, w0); __stcs(ap0 + 1, w1); __stcs(ap0 + 2, w2);
        __stcs(ap1 + 0, w0); __stcs(ap1 + 1, w1); __stcs(ap1 + 2, w2);
    }

    // p_values: offset 6S, shape (2, 28, S); row = p*4 + k*2 + j, value d[p][k]
    float* __restrict__ pv = out + 6 * S;
#pragma unroll
    for (int p = 0; p < 7; p++) {
#pragma unroll
        for (int k = 0; k < 2; k++) {
            float val = d[p][k];
            size_t r = (size_t)(p * 4 + k * 2);
            __stcs(pv + (r + 0) * S + s, val);
            __stcs(pv + (r + 1) * S + s, val);
            __stcs(pv + (r + 28) * S + s, val);
            __stcs(pv + (r + 29) * S + s, val);
        }
    }
}

extern "C" void kernel_launch(void* const* d_in, const int* in_sizes, int n_in,
                              void* d_out, int out_size)
{
    const float* x = (const float*)d_in[0];
    const float* action = (const float*)d_in[1];
    const unsigned char* mask = (const unsigned char*)d_in[2];
    const float* pb = (const float*)d_in[3];
    float* out = (float*)d_out;

    int threads = 512;
    int blocks = (S_TOTAL + threads - 1) / threads;
    ump_kernel<<<blocks, threads>>>(x, action, mask, pb, out);
}